// round 11
// baseline (speedup 1.0000x reference)
#include <cuda_runtime.h>
#include <cuda_fp16.h>

// ---------------- static scratch (no allocation allowed) ----------------
#define N_MAX 100032
#define E_MAX 3400000

__device__ __align__(256) __half d_h1h[100000 * 64]; // h1 * dinv (prescaled), fp16
__device__ __align__(256) float d_z[100000 * 2];     // (relu(g1)@W2f) * dinv
__device__ __align__(256) float d_elog[100000 * 2];  // exp(logits)
__device__ __align__(256) int   d_cnt[N_MAX];        // in-degree histogram (excl self)
__device__ __align__(256) int   d_roff[N_MAX + 1];   // CSR row offsets
__device__ __align__(256) int   d_cursor[N_MAX];     // scatter cursors
__device__ __align__(256) int   d_ssrc[E_MAX];       // src sorted by dst
__device__ __align__(256) long long d_pack[128];     // lookback: (flag<<32)|value
__device__ float d_W2f[64 * 2];                      // W2 @ Wl1 @ Wl2
__device__ float d_bc[2];                            // folded bias
__device__ float d_csum[2];
__device__ unsigned d_bar1, d_bar2, d_bar3;          // monotonic ticket barriers

// ---------------- helpers ----------------
__device__ __forceinline__ void fma2(unsigned long long& d, unsigned long long a, unsigned long long b) {
    asm("fma.rn.f32x2 %0, %1, %2, %0;" : "+l"(d) : "l"(a), "l"(b));
}
__device__ __forceinline__ unsigned long long pk2(float lo, float hi) {
    unsigned long long r;
    asm("mov.b64 %0, {%1, %2};" : "=l"(r) : "f"(lo), "f"(hi));
    return r;
}
__device__ __forceinline__ float2 upk2(unsigned long long v) {
    float2 f;
    asm("mov.b64 {%0, %1}, %2;" : "=f"(f.x), "=f"(f.y) : "l"(v));
    return f;
}

// Replay-safe grid barrier: monotonic counter, ticket rounded up to next
// multiple of G. Requires all G blocks resident (single wave).
__device__ __forceinline__ void ticket_barrier(unsigned* ctr, unsigned G) {
    __syncthreads();
    if (threadIdx.x == 0) {
        __threadfence();
        unsigned a = atomicAdd(ctr, 1u);
        unsigned target = (a / G + 1u) * G;
        while (*((volatile unsigned*)ctr) < target) { }
        __threadfence();
    }
    __syncthreads();
}

// ---------------- CSR build ----------------

// 4 edges per thread via int4; also resets the scan-lookback state.
__global__ void k_hist(const int* __restrict__ dst, int E) {
    int q = blockIdx.x * blockDim.x + threadIdx.x;
    if (q < 128) d_pack[q] = 0;                 // lookback reset (in-stream before scan)
    int e = q * 4;
    if (e + 4 <= E) {
        int4 d4 = *(const int4*)&dst[e];
        atomicAdd(&d_cnt[d4.x], 1);
        atomicAdd(&d_cnt[d4.y], 1);
        atomicAdd(&d_cnt[d4.z], 1);
        atomicAdd(&d_cnt[d4.w], 1);
    } else {
        for (int k = e; k < E; k++) atomicAdd(&d_cnt[dst[k]], 1);
    }
}

// Persistent: decoupled-lookback scan (blocks < nb) -> barrier -> scatter.
// Single wave guaranteed by occupancy-sized G.
__global__ void __launch_bounds__(256)
k_scanscatter(const int* __restrict__ src, const int* __restrict__ dst,
              int E, int n, unsigned G) {
    __shared__ int sh[256];
    __shared__ int s_ex;
    int t = threadIdx.x, b = blockIdx.x;
    int nb = (n + 1023) / 1024;

    if (b < nb) {
        int base = b * 1024 + t * 4;
        int v[4];
        #pragma unroll
        for (int j = 0; j < 4; j++) { int i = base + j; v[j] = (i < n) ? d_cnt[i] : 0; }
        int tsum = v[0] + v[1] + v[2] + v[3];
        sh[t] = tsum; __syncthreads();
        for (int o = 1; o < 256; o <<= 1) {
            int tv = (t >= o) ? sh[t - o] : 0;
            __syncthreads();
            sh[t] += tv;
            __syncthreads();
        }
        int blockAgg = sh[255];

        if (t == 0) {
            long long pk = ((long long)((b == 0) ? 2 : 1) << 32) | (unsigned)blockAgg;
            *((volatile long long*)&d_pack[b]) = pk;
            if (b == 0) s_ex = 0;
        }
        if (b > 0 && t < 32) {          // warp-parallel lookback
            int ex = 0;
            int look = b - 1;
            while (true) {
                int idx = look - t;
                long long pk = 0;
                if (idx >= 0) {
                    do { pk = *((volatile long long*)&d_pack[idx]); } while ((int)(pk >> 32) == 0);
                }
                int flag = (int)(pk >> 32);
                int val  = (int)(unsigned)pk;
                unsigned pm = __ballot_sync(0xffffffffu, flag == 2);
                if (pm) {
                    int fp = __ffs(pm) - 1;
                    int contrib = (t <= fp) ? val : 0;
                    #pragma unroll
                    for (int o = 16; o; o >>= 1) contrib += __shfl_xor_sync(0xffffffffu, contrib, o);
                    ex += contrib;
                    break;
                } else {
                    int contrib = (idx >= 0) ? val : 0;
                    #pragma unroll
                    for (int o = 16; o; o >>= 1) contrib += __shfl_xor_sync(0xffffffffu, contrib, o);
                    ex += contrib;
                    look -= 32;
                }
            }
            if (t == 0) {
                s_ex = ex;
                long long pk = ((long long)2 << 32) | (unsigned)(ex + blockAgg);
                *((volatile long long*)&d_pack[b]) = pk;
            }
        }
        __syncthreads();
        int run = s_ex + sh[t] - tsum;
        #pragma unroll
        for (int j = 0; j < 4; j++) {
            int i = base + j;
            if (i < n) { d_roff[i] = run; d_cursor[i] = run; }
            run += v[j];
        }
        if (b == 0 && t == 0) d_roff[n] = E;
    }

    ticket_barrier(&d_bar1, G);

    // scatter: grid-stride over edge quads
    int quads = (E + 3) / 4;
    int stride = (int)G * 256;
    for (int q = b * 256 + t; q < quads; q += stride) {
        int e = q * 4;
        if (e + 4 <= E) {
            int4 s4 = *(const int4*)&src[e];
            int4 d4 = *(const int4*)&dst[e];
            int p0 = atomicAdd(&d_cursor[d4.x], 1); d_ssrc[p0] = s4.x;
            int p1 = atomicAdd(&d_cursor[d4.y], 1); d_ssrc[p1] = s4.y;
            int p2 = atomicAdd(&d_cursor[d4.z], 1); d_ssrc[p2] = s4.z;
            int p3 = atomicAdd(&d_cursor[d4.w], 1); d_ssrc[p3] = s4.w;
        } else {
            for (int k = e; k < E; k++) {
                int p = atomicAdd(&d_cursor[dst[k]], 1);
                d_ssrc[p] = src[k];
            }
        }
    }
}

// ---------------- dense math ----------------

// h1p = (x @ W1) * dinv[row] -> fp16.  Depends only on d_cnt (histogram).
__global__ void k_gemm1(const float* __restrict__ x, const float* __restrict__ W, int n) {
    __shared__ float xs[64][33];
    __shared__ float ws[32][64];
    int t  = threadIdx.x;
    int ty = t >> 4, tx = t & 15;
    int m0 = blockIdx.x * 64;
    unsigned long long acc[4][2] = {};

    for (int kc = 0; kc < 128; kc += 32) {
        #pragma unroll
        for (int q = 0; q < 2; q++) {                 // x tile: 64x32
            int id = t + q * 256;
            int r = id >> 3;
            int c = (id & 7) * 4;
            int node = m0 + r;
            float4 v = make_float4(0.f, 0.f, 0.f, 0.f);
            if (node < n) v = *(const float4*)&x[node * 128 + kc + c];
            xs[r][c + 0] = v.x; xs[r][c + 1] = v.y;
            xs[r][c + 2] = v.z; xs[r][c + 3] = v.w;
        }
        #pragma unroll
        for (int q = 0; q < 2; q++) {                 // W tile: 32x64
            int id = t + q * 256;
            int r = id >> 4;
            int c = (id & 15) * 4;
            *(float4*)&ws[r][c] = *(const float4*)&W[(kc + r) * 64 + c];
        }
        __syncthreads();
        #pragma unroll
        for (int k = 0; k < 32; k++) {
            float4 b = *(float4*)&ws[k][tx * 4];
            unsigned long long b01 = pk2(b.x, b.y);
            unsigned long long b23 = pk2(b.z, b.w);
            #pragma unroll
            for (int i2 = 0; i2 < 4; i2++) {
                float a = xs[ty * 4 + i2][k];
                unsigned long long aa = pk2(a, a);
                fma2(acc[i2][0], aa, b01);
                fma2(acc[i2][1], aa, b23);
            }
        }
        __syncthreads();
    }
    #pragma unroll
    for (int i2 = 0; i2 < 4; i2++) {
        int node = m0 + ty * 4 + i2;
        if (node < n) {
            float s = rsqrtf((float)d_cnt[node] + 1.0f);   // dinv prescale
            float2 p0 = upk2(acc[i2][0]);
            float2 p1 = upk2(acc[i2][1]);
            __half2* op = (__half2*)&d_h1h[node * 64 + tx * 4];
            op[0] = __floats2half2_rn(p0.x * s, p0.y * s);
            op[1] = __floats2half2_rn(p1.x * s, p1.y * s);
        }
    }
}

// fold W2 @ Wl1 @ Wl2 -> d_W2f; folded bias -> d_bc; reset csum.
__global__ void k_fold(const float* __restrict__ W2, const float* __restrict__ Wl1,
                       const float* __restrict__ Wl2, const float* __restrict__ b2,
                       const float* __restrict__ bl1, const float* __restrict__ bl2) {
    __shared__ float A[64][2];
    int t = threadIdx.x;
    if (t < 128) {                    // stage 1: A = Wl1 @ Wl2
        int i = t >> 1, col = t & 1;
        float a = 0.f;
        #pragma unroll
        for (int m = 0; m < 32; m++)
            a += Wl1[i * 32 + m] * Wl2[m * 2 + col];
        A[i][col] = a;
    }
    if (t == 0) { d_csum[0] = 0.f; d_csum[1] = 0.f; }
    __syncthreads();
    if (t < 128) {                    // stage 2: W2f = W2 @ A
        int i = t >> 1, col = t & 1;
        float f = 0.f;
        #pragma unroll
        for (int j = 0; j < 64; j++)
            f += W2[i * 64 + j] * A[j][col];
        d_W2f[i * 2 + col] = f;
    }
    if (t < 2) {
        float b = bl2[t];
        #pragma unroll
        for (int j = 0; j < 64; j++) b += b2[j] * A[j][t];
        #pragma unroll
        for (int m = 0; m < 32; m++) b += bl1[m] * Wl2[m * 2 + t];
        d_bc[t] = b;
    }
}

// ---------------- persistent aggregation + softmax + output ----------------
// Phase 1: agg1 + relu + projection -> z (+ cnt reset for next replay)
// Phase 2: agg2 -> exp(logits), accumulate csum
// Phase 3: normalize -> out
__global__ void __launch_bounds__(256)
k_aggall(const float* __restrict__ b1, float* __restrict__ out, int n, unsigned G) {
    __shared__ float wf[128];
    __shared__ float red[16];
    int t = threadIdx.x;
    int lane = t & 31;
    int wid  = t >> 5;
    int gidx = blockIdx.x * 256 + t;
    int stride = (int)G * 256;
    int gw0 = gidx >> 5;
    int tw  = stride >> 5;

    if (t < 128) wf[t] = d_W2f[t];
    for (int i = gidx; i < n; i += stride) d_cnt[i] = 0;   // reset for next replay
    __syncthreads();

    // ---- phase 1: z ----
    {
        int c = lane * 2;
        float2 bv = *(const float2*)&b1[c];
        float w00 = wf[2 * c + 0], w01 = wf[2 * c + 1];
        float w10 = wf[2 * c + 2], w11 = wf[2 * c + 3];
        const __half2* hp = (const __half2*)d_h1h;
        for (int w = gw0; w < n; w += tw) {
            int start = d_roff[w];
            int cnt   = d_roff[w + 1] - start;
            float ax = 0.f, ay = 0.f;
            const int* sp = &d_ssrc[start];
            int j = 0;
            for (; j + 8 <= cnt; j += 8) {
                int s0 = __ldg(&sp[j + 0]);
                int s1 = __ldg(&sp[j + 1]);
                int s2 = __ldg(&sp[j + 2]);
                int s3 = __ldg(&sp[j + 3]);
                int s4 = __ldg(&sp[j + 4]);
                int s5 = __ldg(&sp[j + 5]);
                int s6 = __ldg(&sp[j + 6]);
                int s7 = __ldg(&sp[j + 7]);
                float2 a0 = __half22float2(hp[s0 * 32 + lane]);
                float2 a1 = __half22float2(hp[s1 * 32 + lane]);
                float2 a2 = __half22float2(hp[s2 * 32 + lane]);
                float2 a3 = __half22float2(hp[s3 * 32 + lane]);
                float2 a4 = __half22float2(hp[s4 * 32 + lane]);
                float2 a5 = __half22float2(hp[s5 * 32 + lane]);
                float2 a6 = __half22float2(hp[s6 * 32 + lane]);
                float2 a7 = __half22float2(hp[s7 * 32 + lane]);
                ax += ((a0.x + a1.x) + (a2.x + a3.x)) + ((a4.x + a5.x) + (a6.x + a7.x));
                ay += ((a0.y + a1.y) + (a2.y + a3.y)) + ((a4.y + a5.y) + (a6.y + a7.y));
            }
            for (; j < cnt; j++) {
                int s0 = __ldg(&sp[j]);
                float2 a0 = __half22float2(hp[s0 * 32 + lane]);
                ax += a0.x; ay += a0.y;
            }
            float s = rsqrtf((float)cnt + 1.0f);
            float2 self = __half22float2(hp[w * 32 + lane]);
            float gx = fmaxf(s * (ax + self.x) + bv.x, 0.f);
            float gy = fmaxf(s * (ay + self.y) + bv.y, 0.f);
            float z0 = gx * w00 + gy * w10;
            float z1 = gx * w01 + gy * w11;
            #pragma unroll
            for (int o = 16; o; o >>= 1) {
                z0 += __shfl_xor_sync(0xffffffffu, z0, o);
                z1 += __shfl_xor_sync(0xffffffffu, z1, o);
            }
            if (lane == 0)
                ((float2*)d_z)[w] = make_float2(z0 * s, z1 * s);
        }
    }

    ticket_barrier(&d_bar2, G);

    // ---- phase 2: agg2 -> exp(logits), csum ----
    {
        float bc0 = d_bc[0], bc1 = d_bc[1];
        float e0 = 0.f, e1 = 0.f;
        for (int w = gw0; w < n; w += tw) {
            int start = d_roff[w];
            int end   = d_roff[w + 1];
            float z0 = 0.f, z1 = 0.f;
            for (int j = start + lane; j < end; j += 32) {
                int si = __ldg(&d_ssrc[j]);
                float2 zz = ((const float2*)d_z)[si];
                z0 += zz.x; z1 += zz.y;
            }
            #pragma unroll
            for (int o = 16; o; o >>= 1) {
                z0 += __shfl_xor_sync(0xffffffffu, z0, o);
                z1 += __shfl_xor_sync(0xffffffffu, z1, o);
            }
            if (lane == 0) {
                float s = rsqrtf((float)(end - start) + 1.0f);
                float2 self = ((const float2*)d_z)[w];
                float ex0 = expf(s * (z0 + self.x) + bc0);
                float ex1 = expf(s * (z1 + self.y) + bc1);
                ((float2*)d_elog)[w] = make_float2(ex0, ex1);
                e0 += ex0; e1 += ex1;
            }
        }
        #pragma unroll
        for (int o = 16; o; o >>= 1) {
            e0 += __shfl_xor_sync(0xffffffffu, e0, o);
            e1 += __shfl_xor_sync(0xffffffffu, e1, o);
        }
        if (lane == 0) { red[2 * wid] = e0; red[2 * wid + 1] = e1; }
        __syncthreads();
        if (t == 0) {
            float s0 = 0.f, s1 = 0.f;
            #pragma unroll
            for (int q = 0; q < 8; q++) { s0 += red[2 * q]; s1 += red[2 * q + 1]; }
            atomicAdd(&d_csum[0], s0);
            atomicAdd(&d_csum[1], s1);
        }
    }

    ticket_barrier(&d_bar3, G);

    // ---- phase 3: normalize ----
    {
        float r0 = 1.0f / *((volatile float*)&d_csum[0]);
        float r1 = 1.0f / *((volatile float*)&d_csum[1]);
        for (int i = gidx; i < n; i += stride) {
            float2 el = ((const float2*)d_elog)[i];
            out[2 * i + 0] = el.x * r0;
            out[2 * i + 1] = el.y * r1;
        }
    }
}

// ---------------- launch ----------------
extern "C" void kernel_launch(void* const* d_in, const int* in_sizes, int n_in,
                              void* d_out, int out_size) {
    const float* x   = (const float*)d_in[0];
    const int*   ei  = (const int*)d_in[1];     // int32 (JAX x64 disabled)
    const float* W1  = (const float*)d_in[2];
    const float* b1  = (const float*)d_in[3];
    const float* W2  = (const float*)d_in[4];
    const float* b2  = (const float*)d_in[5];
    const float* Wl1 = (const float*)d_in[6];
    const float* bl1 = (const float*)d_in[7];
    const float* Wl2 = (const float*)d_in[8];
    const float* bl2 = (const float*)d_in[9];
    float* out = (float*)d_out;

    int n = in_sizes[0] / 128;
    int E = in_sizes[1] / 2;
    const int* src = ei;
    const int* dst = ei + E;

    static cudaStream_t s1 = 0;
    static cudaEvent_t evFork = 0, evHist = 0, evGemm = 0;
    static unsigned Gss = 0, Gagg = 0;
    if (!s1) {
        cudaStreamCreateWithFlags(&s1, cudaStreamNonBlocking);
        cudaEventCreateWithFlags(&evFork, cudaEventDisableTiming);
        cudaEventCreateWithFlags(&evHist, cudaEventDisableTiming);
        cudaEventCreateWithFlags(&evGemm, cudaEventDisableTiming);
        int dev = 0, sms = 0;
        cudaGetDevice(&dev);
        cudaDeviceGetAttribute(&sms, cudaDevAttrMultiProcessorCount, dev);
        int bss = 0, bagg = 0;
        cudaOccupancyMaxActiveBlocksPerMultiprocessor(&bss, k_scanscatter, 256, 0);
        cudaOccupancyMaxActiveBlocksPerMultiprocessor(&bagg, k_aggall, 256, 0);
        if (bss < 1) bss = 1;
        if (bagg < 1) bagg = 1;
        Gss  = (unsigned)(sms * bss);
        Gagg = (unsigned)(sms * bagg);
        if (Gss > 1184u)  Gss = 1184u;
        if (Gagg > 1184u) Gagg = 1184u;
    }

    // Fork s1 FROM stream 0 so s1 work is captured into the graph.
    cudaEventRecord(evFork, 0);
    cudaStreamWaitEvent(s1, evFork, 0);

    // s1: fold (resets csum; weight folding) — overlaps hist
    k_fold  <<<1, 256, 0, s1>>>(W2, Wl1, Wl2, b2, bl1, bl2);

    // stream 0: hist (+ lookback-state reset)
    k_hist  <<<(E / 4 + 255) / 256, 256>>>(dst, E);
    cudaEventRecord(evHist, 0);

    // s1: gemm (needs d_cnt for prescale) — overlaps scan+scatter
    cudaStreamWaitEvent(s1, evHist, 0);
    k_gemm1 <<<(n + 63) / 64, 256, 0, s1>>>(x, W1, n);
    cudaEventRecord(evGemm, s1);

    // stream 0: persistent scan+scatter
    k_scanscatter<<<Gss, 256>>>(src, dst, E, n, Gss);

    // join
    cudaStreamWaitEvent(0, evGemm, 0);
    k_aggall<<<Gagg, 256>>>(b1, out, n, Gagg);
}

// round 12
// speedup vs baseline: 1.0406x; 1.0406x over previous
#include <cuda_runtime.h>
#include <cuda_fp16.h>

// ---------------- static scratch (no allocation allowed) ----------------
#define N_MAX 100032
#define E_MAX 3400000

__device__ __align__(256) __half d_h1h[100000 * 64]; // h1 * dinv (prescaled), fp16
__device__ __align__(256) float d_z[100000 * 2];     // (relu(g1)@W2f) * dinv
__device__ __align__(256) float d_elog[100000 * 2];  // exp(logits)
__device__ __align__(256) int   d_cnt[N_MAX];        // in-degree histogram (excl self)
__device__ __align__(256) int   d_roff[N_MAX + 1];   // CSR row offsets
__device__ __align__(256) int   d_cursor[N_MAX];     // scatter cursors
__device__ __align__(256) int   d_ssrc[E_MAX];       // src sorted by dst
__device__ __align__(256) long long d_pack[128];     // lookback: (flag<<32)|value
__device__ float d_W2f[64 * 2];                      // W2 @ Wl1 @ Wl2
__device__ float d_bc[2];                            // folded bias
__device__ float d_csum[2];
__device__ unsigned d_bar2, d_bar3;                  // monotonic ticket barriers

// ---------------- helpers ----------------
__device__ __forceinline__ void fma2(unsigned long long& d, unsigned long long a, unsigned long long b) {
    asm("fma.rn.f32x2 %0, %1, %2, %0;" : "+l"(d) : "l"(a), "l"(b));
}
__device__ __forceinline__ unsigned long long pk2(float lo, float hi) {
    unsigned long long r;
    asm("mov.b64 %0, {%1, %2};" : "=l"(r) : "f"(lo), "f"(hi));
    return r;
}
__device__ __forceinline__ float2 upk2(unsigned long long v) {
    float2 f;
    asm("mov.b64 {%0, %1}, %2;" : "=f"(f.x), "=f"(f.y) : "l"(v));
    return f;
}

// Replay-safe grid barrier: monotonic counter, ticket rounded up to next
// multiple of G. Requires all G blocks resident (single wave).
// nanosleep backoff keeps spin traffic off the L2.
__device__ __forceinline__ void ticket_barrier(unsigned* ctr, unsigned G) {
    __syncthreads();
    if (threadIdx.x == 0) {
        __threadfence();
        unsigned a = atomicAdd(ctr, 1u);
        unsigned target = (a / G + 1u) * G;
        while (*((volatile unsigned*)ctr) < target) __nanosleep(128);
        __threadfence();
    }
    __syncthreads();
}

// ---------------- CSR build ----------------

// 4 edges per thread via int4; also resets the scan-lookback state.
__global__ void k_hist(const int* __restrict__ dst, int E) {
    int q = blockIdx.x * blockDim.x + threadIdx.x;
    if (q < 128) d_pack[q] = 0;                 // lookback reset (in-stream before scan)
    int e = q * 4;
    if (e + 4 <= E) {
        int4 d4 = *(const int4*)&dst[e];
        atomicAdd(&d_cnt[d4.x], 1);
        atomicAdd(&d_cnt[d4.y], 1);
        atomicAdd(&d_cnt[d4.z], 1);
        atomicAdd(&d_cnt[d4.w], 1);
    } else {
        for (int k = e; k < E; k++) atomicAdd(&d_cnt[dst[k]], 1);
    }
}

// Single-kernel exclusive scan over d_cnt via decoupled lookback.
// 1024 elems/block, 256 threads. <=98 blocks for n<=100352 (single wave).
__global__ void k_scan(int n, int E) {
    __shared__ int sh[256];
    __shared__ int s_ex;
    int t = threadIdx.x, b = blockIdx.x;
    int base = b * 1024 + t * 4;
    int v[4];
    #pragma unroll
    for (int j = 0; j < 4; j++) { int i = base + j; v[j] = (i < n) ? d_cnt[i] : 0; }
    int tsum = v[0] + v[1] + v[2] + v[3];
    sh[t] = tsum; __syncthreads();
    for (int o = 1; o < 256; o <<= 1) {
        int tv = (t >= o) ? sh[t - o] : 0;
        __syncthreads();
        sh[t] += tv;
        __syncthreads();
    }
    int blockAgg = sh[255];

    if (t == 0) {
        long long pk = ((long long)((b == 0) ? 2 : 1) << 32) | (unsigned)blockAgg;
        *((volatile long long*)&d_pack[b]) = pk;
        if (b == 0) s_ex = 0;
    }
    if (b > 0 && t < 32) {          // warp-parallel lookback
        int ex = 0;
        int look = b - 1;
        while (true) {
            int idx = look - t;
            long long pk = 0;
            if (idx >= 0) {
                do { pk = *((volatile long long*)&d_pack[idx]); } while ((int)(pk >> 32) == 0);
            }
            int flag = (int)(pk >> 32);
            int val  = (int)(unsigned)pk;
            unsigned pm = __ballot_sync(0xffffffffu, flag == 2);
            if (pm) {
                int fp = __ffs(pm) - 1;
                int contrib = (t <= fp) ? val : 0;
                #pragma unroll
                for (int o = 16; o; o >>= 1) contrib += __shfl_xor_sync(0xffffffffu, contrib, o);
                ex += contrib;
                break;
            } else {
                int contrib = (idx >= 0) ? val : 0;
                #pragma unroll
                for (int o = 16; o; o >>= 1) contrib += __shfl_xor_sync(0xffffffffu, contrib, o);
                ex += contrib;
                look -= 32;
            }
        }
        if (t == 0) {
            s_ex = ex;
            long long pk = ((long long)2 << 32) | (unsigned)(ex + blockAgg);
            *((volatile long long*)&d_pack[b]) = pk;
        }
    }
    __syncthreads();
    int run = s_ex + sh[t] - tsum;
    #pragma unroll
    for (int j = 0; j < 4; j++) {
        int i = base + j;
        if (i < n) { d_roff[i] = run; d_cursor[i] = run; }
        run += v[j];
    }
    if (b == 0 && t == 0) d_roff[n] = E;
}

// 4 edges per thread
__global__ void k_scatter(const int* __restrict__ src, const int* __restrict__ dst, int E) {
    int q = blockIdx.x * blockDim.x + threadIdx.x;
    int e = q * 4;
    if (e + 4 <= E) {
        int4 s4 = *(const int4*)&src[e];
        int4 d4 = *(const int4*)&dst[e];
        int p0 = atomicAdd(&d_cursor[d4.x], 1); d_ssrc[p0] = s4.x;
        int p1 = atomicAdd(&d_cursor[d4.y], 1); d_ssrc[p1] = s4.y;
        int p2 = atomicAdd(&d_cursor[d4.z], 1); d_ssrc[p2] = s4.z;
        int p3 = atomicAdd(&d_cursor[d4.w], 1); d_ssrc[p3] = s4.w;
    } else {
        for (int k = e; k < E; k++) {
            int p = atomicAdd(&d_cursor[dst[k]], 1);
            d_ssrc[p] = src[k];
        }
    }
}

// ---------------- dense math ----------------

// h1p = (x @ W1) * dinv[row] -> fp16.  Depends only on d_cnt (histogram).
__global__ void k_gemm1(const float* __restrict__ x, const float* __restrict__ W, int n) {
    __shared__ float xs[64][33];
    __shared__ float ws[32][64];
    int t  = threadIdx.x;
    int ty = t >> 4, tx = t & 15;
    int m0 = blockIdx.x * 64;
    unsigned long long acc[4][2] = {};

    for (int kc = 0; kc < 128; kc += 32) {
        #pragma unroll
        for (int q = 0; q < 2; q++) {                 // x tile: 64x32
            int id = t + q * 256;
            int r = id >> 3;
            int c = (id & 7) * 4;
            int node = m0 + r;
            float4 v = make_float4(0.f, 0.f, 0.f, 0.f);
            if (node < n) v = *(const float4*)&x[node * 128 + kc + c];
            xs[r][c + 0] = v.x; xs[r][c + 1] = v.y;
            xs[r][c + 2] = v.z; xs[r][c + 3] = v.w;
        }
        #pragma unroll
        for (int q = 0; q < 2; q++) {                 // W tile: 32x64
            int id = t + q * 256;
            int r = id >> 4;
            int c = (id & 15) * 4;
            *(float4*)&ws[r][c] = *(const float4*)&W[(kc + r) * 64 + c];
        }
        __syncthreads();
        #pragma unroll
        for (int k = 0; k < 32; k++) {
            float4 b = *(float4*)&ws[k][tx * 4];
            unsigned long long b01 = pk2(b.x, b.y);
            unsigned long long b23 = pk2(b.z, b.w);
            #pragma unroll
            for (int i2 = 0; i2 < 4; i2++) {
                float a = xs[ty * 4 + i2][k];
                unsigned long long aa = pk2(a, a);
                fma2(acc[i2][0], aa, b01);
                fma2(acc[i2][1], aa, b23);
            }
        }
        __syncthreads();
    }
    #pragma unroll
    for (int i2 = 0; i2 < 4; i2++) {
        int node = m0 + ty * 4 + i2;
        if (node < n) {
            float s = rsqrtf((float)d_cnt[node] + 1.0f);   // dinv prescale
            float2 p0 = upk2(acc[i2][0]);
            float2 p1 = upk2(acc[i2][1]);
            __half2* op = (__half2*)&d_h1h[node * 64 + tx * 4];
            op[0] = __floats2half2_rn(p0.x * s, p0.y * s);
            op[1] = __floats2half2_rn(p1.x * s, p1.y * s);
        }
    }
}

// fold W2 @ Wl1 @ Wl2 -> d_W2f; folded bias -> d_bc; reset csum.
__global__ void k_fold(const float* __restrict__ W2, const float* __restrict__ Wl1,
                       const float* __restrict__ Wl2, const float* __restrict__ b2,
                       const float* __restrict__ bl1, const float* __restrict__ bl2) {
    __shared__ float A[64][2];
    int t = threadIdx.x;
    if (t < 128) {                    // stage 1: A = Wl1 @ Wl2
        int i = t >> 1, col = t & 1;
        float a = 0.f;
        #pragma unroll
        for (int m = 0; m < 32; m++)
            a += Wl1[i * 32 + m] * Wl2[m * 2 + col];
        A[i][col] = a;
    }
    if (t == 0) { d_csum[0] = 0.f; d_csum[1] = 0.f; }
    __syncthreads();
    if (t < 128) {                    // stage 2: W2f = W2 @ A
        int i = t >> 1, col = t & 1;
        float f = 0.f;
        #pragma unroll
        for (int j = 0; j < 64; j++)
            f += W2[i * 64 + j] * A[j][col];
        d_W2f[i * 2 + col] = f;
    }
    if (t < 2) {
        float b = bl2[t];
        #pragma unroll
        for (int j = 0; j < 64; j++) b += b2[j] * A[j][t];
        #pragma unroll
        for (int m = 0; m < 32; m++) b += bl1[m] * Wl2[m * 2 + t];
        d_bc[t] = b;
    }
}

// ---------------- persistent aggregation + softmax + output ----------------
// Phase 1: agg1 + relu + projection -> z (+ cnt reset for next replay)
// Phase 2: agg2 -> exp(logits), accumulate csum
// Phase 3: normalize -> out
// All phases use the whole grid (no idle spinners).
__global__ void __launch_bounds__(256)
k_aggall(const float* __restrict__ b1, float* __restrict__ out, int n, unsigned G) {
    __shared__ float wf[128];
    __shared__ float red[16];
    int t = threadIdx.x;
    int lane = t & 31;
    int wid  = t >> 5;
    int gidx = blockIdx.x * 256 + t;
    int stride = (int)G * 256;
    int gw0 = gidx >> 5;
    int tw  = stride >> 5;

    if (t < 128) wf[t] = d_W2f[t];
    for (int i = gidx; i < n; i += stride) d_cnt[i] = 0;   // reset for next replay
    __syncthreads();

    // ---- phase 1: z ----
    {
        int c = lane * 2;
        float2 bv = *(const float2*)&b1[c];
        float w00 = wf[2 * c + 0], w01 = wf[2 * c + 1];
        float w10 = wf[2 * c + 2], w11 = wf[2 * c + 3];
        const __half2* hp = (const __half2*)d_h1h;
        for (int w = gw0; w < n; w += tw) {
            int start = d_roff[w];
            int cnt   = d_roff[w + 1] - start;
            float ax = 0.f, ay = 0.f;
            const int* sp = &d_ssrc[start];
            int j = 0;
            for (; j + 8 <= cnt; j += 8) {
                int s0 = __ldg(&sp[j + 0]);
                int s1 = __ldg(&sp[j + 1]);
                int s2 = __ldg(&sp[j + 2]);
                int s3 = __ldg(&sp[j + 3]);
                int s4 = __ldg(&sp[j + 4]);
                int s5 = __ldg(&sp[j + 5]);
                int s6 = __ldg(&sp[j + 6]);
                int s7 = __ldg(&sp[j + 7]);
                float2 a0 = __half22float2(hp[s0 * 32 + lane]);
                float2 a1 = __half22float2(hp[s1 * 32 + lane]);
                float2 a2 = __half22float2(hp[s2 * 32 + lane]);
                float2 a3 = __half22float2(hp[s3 * 32 + lane]);
                float2 a4 = __half22float2(hp[s4 * 32 + lane]);
                float2 a5 = __half22float2(hp[s5 * 32 + lane]);
                float2 a6 = __half22float2(hp[s6 * 32 + lane]);
                float2 a7 = __half22float2(hp[s7 * 32 + lane]);
                ax += ((a0.x + a1.x) + (a2.x + a3.x)) + ((a4.x + a5.x) + (a6.x + a7.x));
                ay += ((a0.y + a1.y) + (a2.y + a3.y)) + ((a4.y + a5.y) + (a6.y + a7.y));
            }
            for (; j < cnt; j++) {
                int s0 = __ldg(&sp[j]);
                float2 a0 = __half22float2(hp[s0 * 32 + lane]);
                ax += a0.x; ay += a0.y;
            }
            float s = rsqrtf((float)cnt + 1.0f);
            float2 self = __half22float2(hp[w * 32 + lane]);
            float gx = fmaxf(s * (ax + self.x) + bv.x, 0.f);
            float gy = fmaxf(s * (ay + self.y) + bv.y, 0.f);
            float z0 = gx * w00 + gy * w10;
            float z1 = gx * w01 + gy * w11;
            #pragma unroll
            for (int o = 16; o; o >>= 1) {
                z0 += __shfl_xor_sync(0xffffffffu, z0, o);
                z1 += __shfl_xor_sync(0xffffffffu, z1, o);
            }
            if (lane == 0)
                ((float2*)d_z)[w] = make_float2(z0 * s, z1 * s);
        }
    }

    ticket_barrier(&d_bar2, G);

    // ---- phase 2: agg2 -> exp(logits), csum ----
    {
        float bc0 = d_bc[0], bc1 = d_bc[1];
        float e0 = 0.f, e1 = 0.f;
        for (int w = gw0; w < n; w += tw) {
            int start = d_roff[w];
            int end   = d_roff[w + 1];
            float z0 = 0.f, z1 = 0.f;
            for (int j = start + lane; j < end; j += 32) {
                int si = __ldg(&d_ssrc[j]);
                float2 zz = ((const float2*)d_z)[si];
                z0 += zz.x; z1 += zz.y;
            }
            #pragma unroll
            for (int o = 16; o; o >>= 1) {
                z0 += __shfl_xor_sync(0xffffffffu, z0, o);
                z1 += __shfl_xor_sync(0xffffffffu, z1, o);
            }
            if (lane == 0) {
                float s = rsqrtf((float)(end - start) + 1.0f);
                float2 self = ((const float2*)d_z)[w];
                float ex0 = expf(s * (z0 + self.x) + bc0);
                float ex1 = expf(s * (z1 + self.y) + bc1);
                ((float2*)d_elog)[w] = make_float2(ex0, ex1);
                e0 += ex0; e1 += ex1;
            }
        }
        #pragma unroll
        for (int o = 16; o; o >>= 1) {
            e0 += __shfl_xor_sync(0xffffffffu, e0, o);
            e1 += __shfl_xor_sync(0xffffffffu, e1, o);
        }
        if (lane == 0) { red[2 * wid] = e0; red[2 * wid + 1] = e1; }
        __syncthreads();
        if (t == 0) {
            float s0 = 0.f, s1 = 0.f;
            #pragma unroll
            for (int q = 0; q < 8; q++) { s0 += red[2 * q]; s1 += red[2 * q + 1]; }
            atomicAdd(&d_csum[0], s0);
            atomicAdd(&d_csum[1], s1);
        }
    }

    ticket_barrier(&d_bar3, G);

    // ---- phase 3: normalize ----
    {
        float r0 = 1.0f / *((volatile float*)&d_csum[0]);
        float r1 = 1.0f / *((volatile float*)&d_csum[1]);
        for (int i = gidx; i < n; i += stride) {
            float2 el = ((const float2*)d_elog)[i];
            out[2 * i + 0] = el.x * r0;
            out[2 * i + 1] = el.y * r1;
        }
    }
}

// ---------------- launch ----------------
extern "C" void kernel_launch(void* const* d_in, const int* in_sizes, int n_in,
                              void* d_out, int out_size) {
    const float* x   = (const float*)d_in[0];
    const int*   ei  = (const int*)d_in[1];     // int32 (JAX x64 disabled)
    const float* W1  = (const float*)d_in[2];
    const float* b1  = (const float*)d_in[3];
    const float* W2  = (const float*)d_in[4];
    const float* b2  = (const float*)d_in[5];
    const float* Wl1 = (const float*)d_in[6];
    const float* bl1 = (const float*)d_in[7];
    const float* Wl2 = (const float*)d_in[8];
    const float* bl2 = (const float*)d_in[9];
    float* out = (float*)d_out;

    int n = in_sizes[0] / 128;
    int E = in_sizes[1] / 2;
    const int* src = ei;
    const int* dst = ei + E;
    int nb = (n + 1023) / 1024;   // scan blocks (<=98 for n<=100352)

    static cudaStream_t s1 = 0;
    static cudaEvent_t evFork = 0, evHist = 0, evGemm = 0;
    static unsigned Gagg = 0;
    if (!s1) {
        cudaStreamCreateWithFlags(&s1, cudaStreamNonBlocking);
        cudaEventCreateWithFlags(&evFork, cudaEventDisableTiming);
        cudaEventCreateWithFlags(&evHist, cudaEventDisableTiming);
        cudaEventCreateWithFlags(&evGemm, cudaEventDisableTiming);
        int dev = 0, sms = 0;
        cudaGetDevice(&dev);
        cudaDeviceGetAttribute(&sms, cudaDevAttrMultiProcessorCount, dev);
        int bagg = 0;
        cudaOccupancyMaxActiveBlocksPerMultiprocessor(&bagg, k_aggall, 256, 0);
        if (bagg < 1) bagg = 1;
        Gagg = (unsigned)(sms * bagg);
        if (Gagg > 1184u) Gagg = 1184u;
    }

    // Fork s1 FROM stream 0 so s1 work is captured into the graph.
    cudaEventRecord(evFork, 0);
    cudaStreamWaitEvent(s1, evFork, 0);

    // s1: fold (resets csum; weight folding) — overlaps hist
    k_fold  <<<1, 256, 0, s1>>>(W2, Wl1, Wl2, b2, bl1, bl2);

    // stream 0: hist (+ lookback-state reset)
    k_hist  <<<(E / 4 + 255) / 256, 256>>>(dst, E);
    cudaEventRecord(evHist, 0);

    // s1: gemm (needs d_cnt for prescale) — overlaps scan+scatter
    cudaStreamWaitEvent(s1, evHist, 0);
    k_gemm1 <<<(n + 63) / 64, 256, 0, s1>>>(x, W1, n);
    cudaEventRecord(evGemm, s1);

    // stream 0: scan + scatter (separate kernels; no idle spinners)
    k_scan   <<<nb, 256>>>(n, E);
    k_scatter<<<(E / 4 + 255) / 256, 256>>>(src, dst, E);

    // join
    cudaStreamWaitEvent(0, evGemm, 0);
    k_aggall<<<Gagg, 256>>>(b1, out, n, Gagg);
}

// round 13
// speedup vs baseline: 1.1206x; 1.0769x over previous
#include <cuda_runtime.h>
#include <cuda_fp16.h>

// ---------------- static scratch (no allocation allowed) ----------------
#define N_MAX 100032
#define E_MAX 3400000

__device__ __align__(256) __half d_h1h[100000 * 64]; // h1 * dinv (prescaled), fp16
__device__ __align__(256) float d_z[100000 * 2];     // (relu(g1)@W2f) * dinv
__device__ __align__(256) float d_elog[100000 * 2];  // exp(logits)
__device__ __align__(256) int   d_cnt[N_MAX];        // in-degree histogram (excl self)
__device__ __align__(256) int   d_roff[N_MAX + 1];   // CSR row offsets
__device__ __align__(256) int   d_rank[E_MAX];       // per-edge rank within dst bucket
__device__ __align__(256) int   d_ssrc[E_MAX];       // src sorted by dst
__device__ __align__(256) long long d_pack[128];     // lookback: (flag<<32)|value
__device__ float d_W2f[64 * 2];                      // W2 @ Wl1 @ Wl2
__device__ float d_bc[2];                            // folded bias
__device__ float d_csum[2];
__device__ int   d_done;

// ---------------- helpers ----------------
__device__ __forceinline__ void fma2(unsigned long long& d, unsigned long long a, unsigned long long b) {
    asm("fma.rn.f32x2 %0, %1, %2, %0;" : "+l"(d) : "l"(a), "l"(b));
}
__device__ __forceinline__ unsigned long long pk2(float lo, float hi) {
    unsigned long long r;
    asm("mov.b64 %0, {%1, %2};" : "=l"(r) : "f"(lo), "f"(hi));
    return r;
}
__device__ __forceinline__ float2 upk2(unsigned long long v) {
    float2 f;
    asm("mov.b64 {%0, %1}, %2;" : "=f"(f.x), "=f"(f.y) : "l"(v));
    return f;
}

// ---------------- CSR build ----------------

// 4 edges per thread via int4. Records each edge's rank within its dst bucket
// so the scatter pass needs NO atomics. Also resets scan-lookback state.
__global__ void k_hist(const int* __restrict__ dst, int E) {
    int q = blockIdx.x * blockDim.x + threadIdx.x;
    if (q < 128) d_pack[q] = 0;                 // lookback reset (in-stream before scan)
    int e = q * 4;
    if (e + 4 <= E) {
        int4 d4 = *(const int4*)&dst[e];
        int4 r4;
        r4.x = atomicAdd(&d_cnt[d4.x], 1);
        r4.y = atomicAdd(&d_cnt[d4.y], 1);
        r4.z = atomicAdd(&d_cnt[d4.z], 1);
        r4.w = atomicAdd(&d_cnt[d4.w], 1);
        *(int4*)&d_rank[e] = r4;
    } else {
        for (int k = e; k < E; k++) d_rank[k] = atomicAdd(&d_cnt[dst[k]], 1);
    }
}

// Single-kernel exclusive scan over d_cnt via decoupled lookback.
// 1024 elems/block, 256 threads. <=98 blocks for n<=100352 (single wave).
__global__ void k_scan(int n, int E) {
    __shared__ int sh[256];
    __shared__ int s_ex;
    int t = threadIdx.x, b = blockIdx.x;
    int base = b * 1024 + t * 4;
    int v[4];
    #pragma unroll
    for (int j = 0; j < 4; j++) { int i = base + j; v[j] = (i < n) ? d_cnt[i] : 0; }
    int tsum = v[0] + v[1] + v[2] + v[3];
    sh[t] = tsum; __syncthreads();
    for (int o = 1; o < 256; o <<= 1) {
        int tv = (t >= o) ? sh[t - o] : 0;
        __syncthreads();
        sh[t] += tv;
        __syncthreads();
    }
    int blockAgg = sh[255];

    if (t == 0) {
        long long pk = ((long long)((b == 0) ? 2 : 1) << 32) | (unsigned)blockAgg;
        *((volatile long long*)&d_pack[b]) = pk;
        if (b == 0) s_ex = 0;
    }
    if (b > 0 && t < 32) {          // warp-parallel lookback
        int ex = 0;
        int look = b - 1;
        while (true) {
            int idx = look - t;
            long long pk = 0;
            if (idx >= 0) {
                do { pk = *((volatile long long*)&d_pack[idx]); } while ((int)(pk >> 32) == 0);
            }
            int flag = (int)(pk >> 32);
            int val  = (int)(unsigned)pk;
            unsigned pm = __ballot_sync(0xffffffffu, flag == 2);
            if (pm) {
                int fp = __ffs(pm) - 1;
                int contrib = (t <= fp) ? val : 0;
                #pragma unroll
                for (int o = 16; o; o >>= 1) contrib += __shfl_xor_sync(0xffffffffu, contrib, o);
                ex += contrib;
                break;
            } else {
                int contrib = (idx >= 0) ? val : 0;
                #pragma unroll
                for (int o = 16; o; o >>= 1) contrib += __shfl_xor_sync(0xffffffffu, contrib, o);
                ex += contrib;
                look -= 32;
            }
        }
        if (t == 0) {
            s_ex = ex;
            long long pk = ((long long)2 << 32) | (unsigned)(ex + blockAgg);
            *((volatile long long*)&d_pack[b]) = pk;
        }
    }
    __syncthreads();
    int run = s_ex + sh[t] - tsum;
    #pragma unroll
    for (int j = 0; j < 4; j++) {
        int i = base + j;
        if (i < n) d_roff[i] = run;
        run += v[j];
    }
    if (b == 0 && t == 0) d_roff[n] = E;
}

// Atomic-free scatter: position = roff[dst] + rank (recorded during hist).
__global__ void k_scatter(const int* __restrict__ src, const int* __restrict__ dst, int E) {
    int q = blockIdx.x * blockDim.x + threadIdx.x;
    int e = q * 4;
    if (e + 4 <= E) {
        int4 s4 = *(const int4*)&src[e];
        int4 d4 = *(const int4*)&dst[e];
        int4 r4 = *(const int4*)&d_rank[e];
        d_ssrc[d_roff[d4.x] + r4.x] = s4.x;
        d_ssrc[d_roff[d4.y] + r4.y] = s4.y;
        d_ssrc[d_roff[d4.z] + r4.z] = s4.z;
        d_ssrc[d_roff[d4.w] + r4.w] = s4.w;
    } else {
        for (int k = e; k < E; k++)
            d_ssrc[d_roff[dst[k]] + d_rank[k]] = src[k];
    }
}

// ---------------- dense math ----------------

// h1p = (x @ W1) * dinv[row] -> fp16.  Depends only on d_cnt (histogram).
__global__ void k_gemm1(const float* __restrict__ x, const float* __restrict__ W, int n) {
    __shared__ float xs[64][33];
    __shared__ float ws[32][64];
    int t  = threadIdx.x;
    int ty = t >> 4, tx = t & 15;
    int m0 = blockIdx.x * 64;
    unsigned long long acc[4][2] = {};

    for (int kc = 0; kc < 128; kc += 32) {
        #pragma unroll
        for (int q = 0; q < 2; q++) {                 // x tile: 64x32
            int id = t + q * 256;
            int r = id >> 3;
            int c = (id & 7) * 4;
            int node = m0 + r;
            float4 v = make_float4(0.f, 0.f, 0.f, 0.f);
            if (node < n) v = *(const float4*)&x[node * 128 + kc + c];
            xs[r][c + 0] = v.x; xs[r][c + 1] = v.y;
            xs[r][c + 2] = v.z; xs[r][c + 3] = v.w;
        }
        #pragma unroll
        for (int q = 0; q < 2; q++) {                 // W tile: 32x64
            int id = t + q * 256;
            int r = id >> 4;
            int c = (id & 15) * 4;
            *(float4*)&ws[r][c] = *(const float4*)&W[(kc + r) * 64 + c];
        }
        __syncthreads();
        #pragma unroll
        for (int k = 0; k < 32; k++) {
            float4 b = *(float4*)&ws[k][tx * 4];
            unsigned long long b01 = pk2(b.x, b.y);
            unsigned long long b23 = pk2(b.z, b.w);
            #pragma unroll
            for (int i2 = 0; i2 < 4; i2++) {
                float a = xs[ty * 4 + i2][k];
                unsigned long long aa = pk2(a, a);
                fma2(acc[i2][0], aa, b01);
                fma2(acc[i2][1], aa, b23);
            }
        }
        __syncthreads();
    }
    #pragma unroll
    for (int i2 = 0; i2 < 4; i2++) {
        int node = m0 + ty * 4 + i2;
        if (node < n) {
            float s = rsqrtf((float)d_cnt[node] + 1.0f);   // dinv prescale
            float2 p0 = upk2(acc[i2][0]);
            float2 p1 = upk2(acc[i2][1]);
            __half2* op = (__half2*)&d_h1h[node * 64 + tx * 4];
            op[0] = __floats2half2_rn(p0.x * s, p0.y * s);
            op[1] = __floats2half2_rn(p1.x * s, p1.y * s);
        }
    }
}

// fold W2 @ Wl1 @ Wl2 -> d_W2f; folded bias -> d_bc; reset csum + done.
__global__ void k_fold(const float* __restrict__ W2, const float* __restrict__ Wl1,
                       const float* __restrict__ Wl2, const float* __restrict__ b2,
                       const float* __restrict__ bl1, const float* __restrict__ bl2) {
    __shared__ float A[64][2];
    int t = threadIdx.x;
    if (t < 128) {                    // stage 1: A = Wl1 @ Wl2
        int i = t >> 1, col = t & 1;
        float a = 0.f;
        #pragma unroll
        for (int m = 0; m < 32; m++)
            a += Wl1[i * 32 + m] * Wl2[m * 2 + col];
        A[i][col] = a;
    }
    if (t == 0) { d_csum[0] = 0.f; d_csum[1] = 0.f; d_done = 0; }
    __syncthreads();
    if (t < 128) {                    // stage 2: W2f = W2 @ A
        int i = t >> 1, col = t & 1;
        float f = 0.f;
        #pragma unroll
        for (int j = 0; j < 64; j++)
            f += W2[i * 64 + j] * A[j][col];
        d_W2f[i * 2 + col] = f;
    }
    if (t < 2) {
        float b = bl2[t];
        #pragma unroll
        for (int j = 0; j < 64; j++) b += b2[j] * A[j][t];
        #pragma unroll
        for (int m = 0; m < 32; m++) b += bl1[m] * Wl2[m * 2 + t];
        d_bc[t] = b;
    }
}

// ---------------- fused pull-aggregation #1 ----------------
__global__ void k_agg1z(const float* __restrict__ b1, int n) {
    __shared__ float wf[128];
    int gtid = blockIdx.x * blockDim.x + threadIdx.x;
    if (gtid < n) d_cnt[gtid] = 0;               // reset for next replay
    if (threadIdx.x < 128) wf[threadIdx.x] = d_W2f[threadIdx.x];
    __syncthreads();

    int w = gtid >> 5;
    if (w >= n) return;
    int lane = threadIdx.x & 31;
    int c = lane * 2;

    int start = d_roff[w];
    int cnt   = d_roff[w + 1] - start;

    const __half2* hp = (const __half2*)d_h1h;
    float ax = 0.f, ay = 0.f;
    const int* sp = &d_ssrc[start];
    int j = 0;
    for (; j + 8 <= cnt; j += 8) {
        int s0 = __ldg(&sp[j + 0]);
        int s1 = __ldg(&sp[j + 1]);
        int s2 = __ldg(&sp[j + 2]);
        int s3 = __ldg(&sp[j + 3]);
        int s4 = __ldg(&sp[j + 4]);
        int s5 = __ldg(&sp[j + 5]);
        int s6 = __ldg(&sp[j + 6]);
        int s7 = __ldg(&sp[j + 7]);
        float2 a0 = __half22float2(hp[s0 * 32 + lane]);
        float2 a1 = __half22float2(hp[s1 * 32 + lane]);
        float2 a2 = __half22float2(hp[s2 * 32 + lane]);
        float2 a3 = __half22float2(hp[s3 * 32 + lane]);
        float2 a4 = __half22float2(hp[s4 * 32 + lane]);
        float2 a5 = __half22float2(hp[s5 * 32 + lane]);
        float2 a6 = __half22float2(hp[s6 * 32 + lane]);
        float2 a7 = __half22float2(hp[s7 * 32 + lane]);
        ax += ((a0.x + a1.x) + (a2.x + a3.x)) + ((a4.x + a5.x) + (a6.x + a7.x));
        ay += ((a0.y + a1.y) + (a2.y + a3.y)) + ((a4.y + a5.y) + (a6.y + a7.y));
    }
    for (; j < cnt; j++) {
        int s0 = __ldg(&sp[j]);
        float2 a0 = __half22float2(hp[s0 * 32 + lane]);
        ax += a0.x; ay += a0.y;
    }

    float s = rsqrtf((float)cnt + 1.0f);
    float2 self = __half22float2(hp[w * 32 + lane]);
    float2 bv   = *(const float2*)&b1[c];
    float gx = fmaxf(s * (ax + self.x) + bv.x, 0.f);
    float gy = fmaxf(s * (ay + self.y) + bv.y, 0.f);

    float z0 = gx * wf[2 * c + 0] + gy * wf[2 * c + 2];
    float z1 = gx * wf[2 * c + 1] + gy * wf[2 * c + 3];
    #pragma unroll
    for (int o = 16; o; o >>= 1) {
        z0 += __shfl_xor_sync(0xffffffffu, z0, o);
        z1 += __shfl_xor_sync(0xffffffffu, z1, o);
    }
    if (lane == 0)
        ((float2*)d_z)[w] = make_float2(z0 * s, z1 * s);
}

// ---------------- persistent agg2 + softmax + output ----------------
// grid = SMs*4 blocks of 256 (single wave guaranteed) -> spin barrier is safe.
__global__ void __launch_bounds__(256)
k_agg2out(float* __restrict__ out, int n, int G) {
    __shared__ float red[16];
    int lane = threadIdx.x & 31;
    int wid  = threadIdx.x >> 5;
    int gw0  = (blockIdx.x * blockDim.x + threadIdx.x) >> 5;
    int tw   = (gridDim.x * blockDim.x) >> 5;

    float bc0 = d_bc[0], bc1 = d_bc[1];
    float e0 = 0.f, e1 = 0.f;
    for (int w = gw0; w < n; w += tw) {
        int start = d_roff[w];
        int end   = d_roff[w + 1];
        float z0 = 0.f, z1 = 0.f;
        for (int j = start + lane; j < end; j += 32) {
            int si = __ldg(&d_ssrc[j]);
            float2 zz = ((const float2*)d_z)[si];
            z0 += zz.x; z1 += zz.y;
        }
        #pragma unroll
        for (int o = 16; o; o >>= 1) {
            z0 += __shfl_xor_sync(0xffffffffu, z0, o);
            z1 += __shfl_xor_sync(0xffffffffu, z1, o);
        }
        if (lane == 0) {
            float s = rsqrtf((float)(end - start) + 1.0f);
            float2 self = ((const float2*)d_z)[w];
            float ex0 = expf(s * (z0 + self.x) + bc0);
            float ex1 = expf(s * (z1 + self.y) + bc1);
            ((float2*)d_elog)[w] = make_float2(ex0, ex1);
            e0 += ex0; e1 += ex1;
        }
    }
    #pragma unroll
    for (int o = 16; o; o >>= 1) {
        e0 += __shfl_xor_sync(0xffffffffu, e0, o);
        e1 += __shfl_xor_sync(0xffffffffu, e1, o);
    }
    if (lane == 0) { red[2 * wid] = e0; red[2 * wid + 1] = e1; }
    __syncthreads();
    if (threadIdx.x == 0) {
        float s0 = 0.f, s1 = 0.f;
        #pragma unroll
        for (int q = 0; q < 8; q++) { s0 += red[2 * q]; s1 += red[2 * q + 1]; }
        atomicAdd(&d_csum[0], s0);
        atomicAdd(&d_csum[1], s1);
        __threadfence();
        atomicAdd(&d_done, 1);
        while (*((volatile int*)&d_done) < G) __nanosleep(64);
    }
    __syncthreads();
    __threadfence();
    float r0 = 1.0f / *((volatile float*)&d_csum[0]);
    float r1 = 1.0f / *((volatile float*)&d_csum[1]);
    for (int i = blockIdx.x * blockDim.x + threadIdx.x; i < n; i += gridDim.x * blockDim.x) {
        float2 el = ((const float2*)d_elog)[i];
        out[2 * i + 0] = el.x * r0;
        out[2 * i + 1] = el.y * r1;
    }
}

// ---------------- launch ----------------
extern "C" void kernel_launch(void* const* d_in, const int* in_sizes, int n_in,
                              void* d_out, int out_size) {
    const float* x   = (const float*)d_in[0];
    const int*   ei  = (const int*)d_in[1];     // int32 (JAX x64 disabled)
    const float* W1  = (const float*)d_in[2];
    const float* b1  = (const float*)d_in[3];
    const float* W2  = (const float*)d_in[4];
    const float* b2  = (const float*)d_in[5];
    const float* Wl1 = (const float*)d_in[6];
    const float* bl1 = (const float*)d_in[7];
    const float* Wl2 = (const float*)d_in[8];
    const float* bl2 = (const float*)d_in[9];
    float* out = (float*)d_out;

    int n = in_sizes[0] / 128;
    int E = in_sizes[1] / 2;
    const int* src = ei;
    const int* dst = ei + E;
    int nb = (n + 1023) / 1024;   // scan blocks (<=98 for n<=100352)

    static cudaStream_t s1 = 0;
    static cudaEvent_t evFork = 0, evHist = 0, evGemm = 0;
    static int G = 0;
    if (!s1) {
        cudaStreamCreateWithFlags(&s1, cudaStreamNonBlocking);
        cudaEventCreateWithFlags(&evFork, cudaEventDisableTiming);
        cudaEventCreateWithFlags(&evHist, cudaEventDisableTiming);
        cudaEventCreateWithFlags(&evGemm, cudaEventDisableTiming);
        int dev = 0, sms = 0;
        cudaGetDevice(&dev);
        cudaDeviceGetAttribute(&sms, cudaDevAttrMultiProcessorCount, dev);
        G = sms * 4;               // 256 thr/block -> guaranteed single wave
    }

    // Fork s1 FROM stream 0 so s1 work is captured into the graph.
    cudaEventRecord(evFork, 0);
    cudaStreamWaitEvent(s1, evFork, 0);

    // s1: fold (resets csum/done; weight folding) — overlaps hist
    k_fold  <<<1, 256, 0, s1>>>(W2, Wl1, Wl2, b2, bl1, bl2);

    // stream 0: hist (+ rank recording + lookback-state reset)
    k_hist  <<<(E / 4 + 255) / 256, 256>>>(dst, E);
    cudaEventRecord(evHist, 0);

    // s1: gemm (needs d_cnt for prescale) — overlaps scan + scatter
    cudaStreamWaitEvent(s1, evHist, 0);
    k_gemm1 <<<(n + 63) / 64, 256, 0, s1>>>(x, W1, n);
    cudaEventRecord(evGemm, s1);

    // stream 0: single-kernel scan + atomic-free scatter
    k_scan   <<<nb, 256>>>(n, E);
    k_scatter<<<(E / 4 + 255) / 256, 256>>>(src, dst, E);

    // join
    cudaStreamWaitEvent(0, evGemm, 0);
    k_agg1z  <<<(n * 32 + 255) / 256, 256>>>(b1, n);
    k_agg2out<<<G, 256>>>(out, n, G);
}

// round 15
// speedup vs baseline: 1.1329x; 1.0109x over previous
#include <cuda_runtime.h>
#include <cuda_fp16.h>

// ---------------- static scratch (no allocation allowed) ----------------
#define N_MAX 100032
#define E_MAX 3400000

__device__ __align__(256) __half d_h1h[100000 * 64]; // h1 (raw, then *dinv in-place), fp16
__device__ __align__(256) float d_z[100000 * 2];     // (relu(g1)@W2f) * dinv
__device__ __align__(256) float d_elog[100000 * 2];  // exp(logits)
__device__ __align__(256) int   d_cnt[N_MAX];        // in-degree histogram (excl self)
__device__ __align__(256) int   d_roff[N_MAX + 1];   // CSR row offsets
__device__ __align__(256) int   d_rank[E_MAX];       // per-edge rank within dst bucket
__device__ __align__(256) int   d_ssrc[E_MAX];       // src sorted by dst
__device__ __align__(256) long long d_pack[128];     // lookback: (flag<<32)|value
__device__ float d_W2f[64 * 2];                      // W2 @ Wl1 @ Wl2
__device__ float d_bc[2];                            // folded bias
__device__ float d_csum[2];
__device__ int   d_done;

// ---------------- helpers ----------------
__device__ __forceinline__ void fma2(unsigned long long& d, unsigned long long a, unsigned long long b) {
    asm("fma.rn.f32x2 %0, %1, %2, %0;" : "+l"(d) : "l"(a), "l"(b));
}
__device__ __forceinline__ unsigned long long pk2(float lo, float hi) {
    unsigned long long r;
    asm("mov.b64 %0, {%1, %2};" : "=l"(r) : "f"(lo), "f"(hi));
    return r;
}
__device__ __forceinline__ float2 upk2(unsigned long long v) {
    float2 f;
    asm("mov.b64 {%0, %1}, %2;" : "=f"(f.x), "=f"(f.y) : "l"(v));
    return f;
}

// ---------------- CSR build ----------------

// 4 edges per thread via int4. Records each edge's rank within its dst bucket
// so the scatter pass needs NO atomics. Also resets scan-lookback state.
__global__ void k_hist(const int* __restrict__ dst, int E) {
    int q = blockIdx.x * blockDim.x + threadIdx.x;
    if (q < 128) d_pack[q] = 0;                 // lookback reset (in-stream before scan)
    int e = q * 4;
    if (e + 4 <= E) {
        int4 d4 = *(const int4*)&dst[e];
        int4 r4;
        r4.x = atomicAdd(&d_cnt[d4.x], 1);
        r4.y = atomicAdd(&d_cnt[d4.y], 1);
        r4.z = atomicAdd(&d_cnt[d4.z], 1);
        r4.w = atomicAdd(&d_cnt[d4.w], 1);
        *(int4*)&d_rank[e] = r4;
    } else {
        for (int k = e; k < E; k++) d_rank[k] = atomicAdd(&d_cnt[dst[k]], 1);
    }
}

// Single-kernel exclusive scan over d_cnt via decoupled lookback.
// 1024 elems/block, 256 threads. <=98 blocks for n<=100352 (single wave).
__global__ void k_scan(int n, int E) {
    __shared__ int sh[256];
    __shared__ int s_ex;
    int t = threadIdx.x, b = blockIdx.x;
    int base = b * 1024 + t * 4;
    int v[4];
    #pragma unroll
    for (int j = 0; j < 4; j++) { int i = base + j; v[j] = (i < n) ? d_cnt[i] : 0; }
    int tsum = v[0] + v[1] + v[2] + v[3];
    sh[t] = tsum; __syncthreads();
    for (int o = 1; o < 256; o <<= 1) {
        int tv = (t >= o) ? sh[t - o] : 0;
        __syncthreads();
        sh[t] += tv;
        __syncthreads();
    }
    int blockAgg = sh[255];

    if (t == 0) {
        long long pk = ((long long)((b == 0) ? 2 : 1) << 32) | (unsigned)blockAgg;
        *((volatile long long*)&d_pack[b]) = pk;
        if (b == 0) s_ex = 0;
    }
    if (b > 0 && t < 32) {          // warp-parallel lookback
        int ex = 0;
        int look = b - 1;
        while (true) {
            int idx = look - t;
            long long pk = 0;
            if (idx >= 0) {
                do { pk = *((volatile long long*)&d_pack[idx]); } while ((int)(pk >> 32) == 0);
            }
            int flag = (int)(pk >> 32);
            int val  = (int)(unsigned)pk;
            unsigned pm = __ballot_sync(0xffffffffu, flag == 2);
            if (pm) {
                int fp = __ffs(pm) - 1;
                int contrib = (t <= fp) ? val : 0;
                #pragma unroll
                for (int o = 16; o; o >>= 1) contrib += __shfl_xor_sync(0xffffffffu, contrib, o);
                ex += contrib;
                break;
            } else {
                int contrib = (idx >= 0) ? val : 0;
                #pragma unroll
                for (int o = 16; o; o >>= 1) contrib += __shfl_xor_sync(0xffffffffu, contrib, o);
                ex += contrib;
                look -= 32;
            }
        }
        if (t == 0) {
            s_ex = ex;
            long long pk = ((long long)2 << 32) | (unsigned)(ex + blockAgg);
            *((volatile long long*)&d_pack[b]) = pk;
        }
    }
    __syncthreads();
    int run = s_ex + sh[t] - tsum;
    #pragma unroll
    for (int j = 0; j < 4; j++) {
        int i = base + j;
        if (i < n) d_roff[i] = run;
        run += v[j];
    }
    if (b == 0 && t == 0) d_roff[n] = E;
}

// Atomic-free scatter: position = roff[dst] + rank (recorded during hist).
__global__ void k_scatter(const int* __restrict__ src, const int* __restrict__ dst, int E) {
    int q = blockIdx.x * blockDim.x + threadIdx.x;
    int e = q * 4;
    if (e + 4 <= E) {
        int4 s4 = *(const int4*)&src[e];
        int4 d4 = *(const int4*)&dst[e];
        int4 r4 = *(const int4*)&d_rank[e];
        d_ssrc[d_roff[d4.x] + r4.x] = s4.x;
        d_ssrc[d_roff[d4.y] + r4.y] = s4.y;
        d_ssrc[d_roff[d4.z] + r4.z] = s4.z;
        d_ssrc[d_roff[d4.w] + r4.w] = s4.w;
    } else {
        for (int k = e; k < E; k++)
            d_ssrc[d_roff[dst[k]] + d_rank[k]] = src[k];
    }
}

// ---------------- dense math ----------------

// h1 = x @ W1 -> fp16 (UNSCALED).  No input dependencies -> starts at t=0.
__global__ void k_gemm1(const float* __restrict__ x, const float* __restrict__ W, int n) {
    __shared__ float xs[64][33];
    __shared__ float ws[32][64];
    int t  = threadIdx.x;
    int ty = t >> 4, tx = t & 15;
    int m0 = blockIdx.x * 64;
    unsigned long long acc[4][2] = {};

    for (int kc = 0; kc < 128; kc += 32) {
        #pragma unroll
        for (int q = 0; q < 2; q++) {                 // x tile: 64x32
            int id = t + q * 256;
            int r = id >> 3;
            int c = (id & 7) * 4;
            int node = m0 + r;
            float4 v = make_float4(0.f, 0.f, 0.f, 0.f);
            if (node < n) v = *(const float4*)&x[node * 128 + kc + c];
            xs[r][c + 0] = v.x; xs[r][c + 1] = v.y;
            xs[r][c + 2] = v.z; xs[r][c + 3] = v.w;
        }
        #pragma unroll
        for (int q = 0; q < 2; q++) {                 // W tile: 32x64
            int id = t + q * 256;
            int r = id >> 4;
            int c = (id & 15) * 4;
            *(float4*)&ws[r][c] = *(const float4*)&W[(kc + r) * 64 + c];
        }
        __syncthreads();
        #pragma unroll
        for (int k = 0; k < 32; k++) {
            float4 b = *(float4*)&ws[k][tx * 4];
            unsigned long long b01 = pk2(b.x, b.y);
            unsigned long long b23 = pk2(b.z, b.w);
            #pragma unroll
            for (int i2 = 0; i2 < 4; i2++) {
                float a = xs[ty * 4 + i2][k];
                unsigned long long aa = pk2(a, a);
                fma2(acc[i2][0], aa, b01);
                fma2(acc[i2][1], aa, b23);
            }
        }
        __syncthreads();
    }
    #pragma unroll
    for (int i2 = 0; i2 < 4; i2++) {
        int node = m0 + ty * 4 + i2;
        if (node < n) {
            float2 p0 = upk2(acc[i2][0]);
            float2 p1 = upk2(acc[i2][1]);
            __half2* op = (__half2*)&d_h1h[node * 64 + tx * 4];
            op[0] = __floats2half2_rn(p0.x, p0.y);
            op[1] = __floats2half2_rn(p1.x, p1.y);
        }
    }
}

// In-place prescale: h1h[node,:] *= rsqrt(cnt[node]+1).  Streaming, ~4us.
// One float4 = 8 halfs per thread; a 64-half row = 8 chunks -> node = idx>>3.
__global__ void k_scale(int n8) {
    int idx = blockIdx.x * blockDim.x + threadIdx.x;
    if (idx >= n8) return;
    int node = idx >> 3;
    float s = rsqrtf((float)d_cnt[node] + 1.0f);
    float4* p = (float4*)d_h1h + idx;
    float4 v = *p;
    __half2* h = (__half2*)&v;
    #pragma unroll
    for (int q = 0; q < 4; q++) {
        float2 f = __half22float2(h[q]);
        h[q] = __floats2half2_rn(f.x * s, f.y * s);
    }
    *p = v;
}

// fold W2 @ Wl1 @ Wl2 -> d_W2f; folded bias -> d_bc; reset csum + done.
__global__ void k_fold(const float* __restrict__ W2, const float* __restrict__ Wl1,
                       const float* __restrict__ Wl2, const float* __restrict__ b2,
                       const float* __restrict__ bl1, const float* __restrict__ bl2) {
    __shared__ float A[64][2];
    int t = threadIdx.x;
    if (t < 128) {                    // stage 1: A = Wl1 @ Wl2
        int i = t >> 1, col = t & 1;
        float a = 0.f;
        #pragma unroll
        for (int m = 0; m < 32; m++)
            a += Wl1[i * 32 + m] * Wl2[m * 2 + col];
        A[i][col] = a;
    }
    if (t == 0) { d_csum[0] = 0.f; d_csum[1] = 0.f; d_done = 0; }
    __syncthreads();
    if (t < 128) {                    // stage 2: W2f = W2 @ A
        int i = t >> 1, col = t & 1;
        float f = 0.f;
        #pragma unroll
        for (int j = 0; j < 64; j++)
            f += W2[i * 64 + j] * A[j][col];
        d_W2f[i * 2 + col] = f;
    }
    if (t < 2) {
        float b = bl2[t];
        #pragma unroll
        for (int j = 0; j < 64; j++) b += b2[j] * A[j][t];
        #pragma unroll
        for (int m = 0; m < 32; m++) b += bl1[m] * Wl2[m * 2 + t];
        d_bc[t] = b;
    }
}

// ---------------- fused pull-aggregation #1 ----------------
__global__ void k_agg1z(const float* __restrict__ b1, int n) {
    __shared__ float wf[128];
    int gtid = blockIdx.x * blockDim.x + threadIdx.x;
    if (gtid < n) d_cnt[gtid] = 0;               // reset for next replay
    if (threadIdx.x < 128) wf[threadIdx.x] = d_W2f[threadIdx.x];
    __syncthreads();

    int w = gtid >> 5;
    if (w >= n) return;
    int lane = threadIdx.x & 31;
    int c = lane * 2;

    int start = d_roff[w];
    int cnt   = d_roff[w + 1] - start;

    const __half2* hp = (const __half2*)d_h1h;
    float ax = 0.f, ay = 0.f;
    const int* sp = &d_ssrc[start];
    int j = 0;
    for (; j + 8 <= cnt; j += 8) {
        int s0 = __ldg(&sp[j + 0]);
        int s1 = __ldg(&sp[j + 1]);
        int s2 = __ldg(&sp[j + 2]);
        int s3 = __ldg(&sp[j + 3]);
        int s4 = __ldg(&sp[j + 4]);
        int s5 = __ldg(&sp[j + 5]);
        int s6 = __ldg(&sp[j + 6]);
        int s7 = __ldg(&sp[j + 7]);
        float2 a0 = __half22float2(hp[s0 * 32 + lane]);
        float2 a1 = __half22float2(hp[s1 * 32 + lane]);
        float2 a2 = __half22float2(hp[s2 * 32 + lane]);
        float2 a3 = __half22float2(hp[s3 * 32 + lane]);
        float2 a4 = __half22float2(hp[s4 * 32 + lane]);
        float2 a5 = __half22float2(hp[s5 * 32 + lane]);
        float2 a6 = __half22float2(hp[s6 * 32 + lane]);
        float2 a7 = __half22float2(hp[s7 * 32 + lane]);
        ax += ((a0.x + a1.x) + (a2.x + a3.x)) + ((a4.x + a5.x) + (a6.x + a7.x));
        ay += ((a0.y + a1.y) + (a2.y + a3.y)) + ((a4.y + a5.y) + (a6.y + a7.y));
    }
    for (; j < cnt; j++) {
        int s0 = __ldg(&sp[j]);
        float2 a0 = __half22float2(hp[s0 * 32 + lane]);
        ax += a0.x; ay += a0.y;
    }

    float s = rsqrtf((float)cnt + 1.0f);
    float2 self = __half22float2(hp[w * 32 + lane]);
    float2 bv   = *(const float2*)&b1[c];
    float gx = fmaxf(s * (ax + self.x) + bv.x, 0.f);
    float gy = fmaxf(s * (ay + self.y) + bv.y, 0.f);

    float z0 = gx * wf[2 * c + 0] + gy * wf[2 * c + 2];
    float z1 = gx * wf[2 * c + 1] + gy * wf[2 * c + 3];
    #pragma unroll
    for (int o = 16; o; o >>= 1) {
        z0 += __shfl_xor_sync(0xffffffffu, z0, o);
        z1 += __shfl_xor_sync(0xffffffffu, z1, o);
    }
    if (lane == 0)
        ((float2*)d_z)[w] = make_float2(z0 * s, z1 * s);
}

// ---------------- persistent agg2 + softmax + output ----------------
// grid = SMs*4 blocks of 256 (single wave guaranteed) -> spin barrier is safe.
__global__ void __launch_bounds__(256)
k_agg2out(float* __restrict__ out, int n, int G) {
    __shared__ float red[16];
    int lane = threadIdx.x & 31;
    int wid  = threadIdx.x >> 5;
    int gw0  = (blockIdx.x * blockDim.x + threadIdx.x) >> 5;
    int tw   = (gridDim.x * blockDim.x) >> 5;

    float bc0 = d_bc[0], bc1 = d_bc[1];
    float e0 = 0.f, e1 = 0.f;
    for (int w = gw0; w < n; w += tw) {
        int start = d_roff[w];
        int end   = d_roff[w + 1];
        float z0 = 0.f, z1 = 0.f;
        for (int j = start + lane; j < end; j += 32) {
            int si = __ldg(&d_ssrc[j]);
            float2 zz = ((const float2*)d_z)[si];
            z0 += zz.x; z1 += zz.y;
        }
        #pragma unroll
        for (int o = 16; o; o >>= 1) {
            z0 += __shfl_xor_sync(0xffffffffu, z0, o);
            z1 += __shfl_xor_sync(0xffffffffu, z1, o);
        }
        if (lane == 0) {
            float s = rsqrtf((float)(end - start) + 1.0f);
            float2 self = ((const float2*)d_z)[w];
            float ex0 = expf(s * (z0 + self.x) + bc0);
            float ex1 = expf(s * (z1 + self.y) + bc1);
            ((float2*)d_elog)[w] = make_float2(ex0, ex1);
            e0 += ex0; e1 += ex1;
        }
    }
    #pragma unroll
    for (int o = 16; o; o >>= 1) {
        e0 += __shfl_xor_sync(0xffffffffu, e0, o);
        e1 += __shfl_xor_sync(0xffffffffu, e1, o);
    }
    if (lane == 0) { red[2 * wid] = e0; red[2 * wid + 1] = e1; }
    __syncthreads();
    if (threadIdx.x == 0) {
        float s0 = 0.f, s1 = 0.f;
        #pragma unroll
        for (int q = 0; q < 8; q++) { s0 += red[2 * q]; s1 += red[2 * q + 1]; }
        atomicAdd(&d_csum[0], s0);
        atomicAdd(&d_csum[1], s1);
        __threadfence();
        atomicAdd(&d_done, 1);
        while (*((volatile int*)&d_done) < G) __nanosleep(64);
    }
    __syncthreads();
    __threadfence();
    float r0 = 1.0f / *((volatile float*)&d_csum[0]);
    float r1 = 1.0f / *((volatile float*)&d_csum[1]);
    for (int i = blockIdx.x * blockDim.x + threadIdx.x; i < n; i += gridDim.x * blockDim.x) {
        float2 el = ((const float2*)d_elog)[i];
        out[2 * i + 0] = el.x * r0;
        out[2 * i + 1] = el.y * r1;
    }
}

// ---------------- launch ----------------
extern "C" void kernel_launch(void* const* d_in, const int* in_sizes, int n_in,
                              void* d_out, int out_size) {
    const float* x   = (const float*)d_in[0];
    const int*   ei  = (const int*)d_in[1];     // int32 (JAX x64 disabled)
    const float* W1  = (const float*)d_in[2];
    const float* b1  = (const float*)d_in[3];
    const float* W2  = (const float*)d_in[4];
    const float* b2  = (const float*)d_in[5];
    const float* Wl1 = (const float*)d_in[6];
    const float* bl1 = (const float*)d_in[7];
    const float* Wl2 = (const float*)d_in[8];
    const float* bl2 = (const float*)d_in[9];
    float* out = (float*)d_out;

    int n = in_sizes[0] / 128;
    int E = in_sizes[1] / 2;
    const int* src = ei;
    const int* dst = ei + E;
    int nb = (n + 1023) / 1024;   // scan blocks (<=98 for n<=100352)
    int n8 = n * 8;               // float4 chunks of h1h (8 per 64-half row)

    static cudaStream_t s1 = 0;
    static cudaEvent_t evFork = 0, evHist = 0, evScale = 0;
    static int G = 0;
    if (!s1) {
        cudaStreamCreateWithFlags(&s1, cudaStreamNonBlocking);
        cudaEventCreateWithFlags(&evFork, cudaEventDisableTiming);
        cudaEventCreateWithFlags(&evHist, cudaEventDisableTiming);
        cudaEventCreateWithFlags(&evScale, cudaEventDisableTiming);
        int dev = 0, sms = 0;
        cudaGetDevice(&dev);
        cudaDeviceGetAttribute(&sms, cudaDevAttrMultiProcessorCount, dev);
        G = sms * 4;               // 256 thr/block -> guaranteed single wave
    }

    // Fork s1 FROM stream 0 so s1 work is captured into the graph.
    cudaEventRecord(evFork, 0);
    cudaStreamWaitEvent(s1, evFork, 0);

    // s1: gemm (NO deps -> starts at t=0, overlaps hist) + fold
    k_gemm1 <<<(n + 63) / 64, 256, 0, s1>>>(x, W1, n);
    k_fold  <<<1, 256, 0, s1>>>(W2, Wl1, Wl2, b2, bl1, bl2);

    // stream 0: hist (+ rank recording + lookback-state reset)
    k_hist  <<<(E / 4 + 255) / 256, 256>>>(dst, E);
    cudaEventRecord(evHist, 0);

    // s1: prescale h1 in place (needs gemm [in-stream] + hist [event])
    cudaStreamWaitEvent(s1, evHist, 0);
    k_scale <<<(n8 + 255) / 256, 256, 0, s1>>>(n8);
    cudaEventRecord(evScale, s1);

    // stream 0: single-kernel scan + atomic-free scatter
    k_scan   <<<nb, 256>>>(n, E);
    k_scatter<<<(E / 4 + 255) / 256, 256>>>(src, dst, E);

    // join
    cudaStreamWaitEvent(0, evScale, 0);
    k_agg1z  <<<(n * 32 + 255) / 256, 256>>>(b1, n);
    k_agg2out<<<G, 256>>>(out, n, G);
}